// round 1
// baseline (speedup 1.0000x reference)
#include <cuda_runtime.h>
#include <math.h>

#define BB 4
#define SS 1024
#define DD 1024
#define HH 16
#define DKK 64

// Scratch (static device globals — no runtime allocation)
__device__ float g_WGK[DD * DD];        // W_G @ Wk            (4 MB)
__device__ float g_biask[DD];           // b_G @ Wk + bk
__device__ float g_g0[BB * DD];         // X[:,0,:] @ W_G + b_G
__device__ float g_q0[BB * DD];         // g0 @ Wq + bq  (rope@pos0 = identity)
__device__ float g_Kw[BB * SS * DD];    // rope(X @ WGK + biask)  (16 MB)
__device__ float g_row0[BB * HH * SS];  // softmax row 0

// ---------------------------------------------------------------------------
// Small GEMV: out[b*1024+j] = bias[j] + sum_i x[b*xstride + i] * W[i*1024 + j]
// grid (32, nbatch), 32 threads
// ---------------------------------------------------------------------------
__global__ void gemv_kernel(const float* __restrict__ x,
                            const float* __restrict__ W,
                            const float* __restrict__ bv,
                            float* __restrict__ out,
                            long long xstride)
{
    int b = blockIdx.y;
    int j = blockIdx.x * 32 + threadIdx.x;
    const float* xr = x + (long long)b * xstride;
    float acc = bv[j];
#pragma unroll 8
    for (int i = 0; i < 1024; i++)
        acc = fmaf(xr[i], W[(long long)i * 1024 + j], acc);
    out[b * 1024 + j] = acc;
}

// ---------------------------------------------------------------------------
// SGEMM 128x128x8, 256 threads, 8x8 thread tile. N = K = 1024 fixed.
// C[M,1024] = A[M,1024] @ B[1024,1024]  (+bias, + optional k-RoPE epilogue)
// rope epilogue: row pos = (global row) & 1023; per even column pair (2p,2p+1)
//   within a head: kw0 = v0*cos - v1*sin ; kw1 = v1*cos + v0*sin
// ---------------------------------------------------------------------------
__global__ __launch_bounds__(256) void sgemm128(const float* __restrict__ A,
                                                const float* __restrict__ Bm,
                                                const float* __restrict__ bias,
                                                float* __restrict__ C,
                                                int rope)
{
    __shared__ float As[8][128];
    __shared__ float Bs[8][128];
    const int tid = threadIdx.x;
    const int m0 = blockIdx.y * 128;
    const int n0 = blockIdx.x * 128;

    const int arow = tid >> 1;         // 0..127
    const int acol = (tid & 1) * 4;    // 0 or 4
    const int brow = tid >> 5;         // 0..7
    const int bcol = (tid & 31) * 4;   // 0..124

    const int tr = (tid >> 4) * 8;     // 0..120
    const int tc = (tid & 15) * 8;     // 0..120

    float acc[8][8];
#pragma unroll
    for (int i = 0; i < 8; i++)
#pragma unroll
        for (int j = 0; j < 8; j++) acc[i][j] = 0.f;

    const float* Ag = A + (long long)(m0 + arow) * 1024 + acol;
    const float* Bg = Bm + (long long)brow * 1024 + n0 + bcol;

    for (int k0 = 0; k0 < 1024; k0 += 8) {
        float4 a4 = *(const float4*)(Ag + k0);
        float4 b4 = *(const float4*)(Bg + (long long)k0 * 1024);
        As[acol + 0][arow] = a4.x;
        As[acol + 1][arow] = a4.y;
        As[acol + 2][arow] = a4.z;
        As[acol + 3][arow] = a4.w;
        *(float4*)&Bs[brow][bcol] = b4;
        __syncthreads();
#pragma unroll
        for (int kk = 0; kk < 8; kk++) {
            float ar[8], br[8];
            *(float4*)(ar)     = *(const float4*)&As[kk][tr];
            *(float4*)(ar + 4) = *(const float4*)&As[kk][tr + 4];
            *(float4*)(br)     = *(const float4*)&Bs[kk][tc];
            *(float4*)(br + 4) = *(const float4*)&Bs[kk][tc + 4];
#pragma unroll
            for (int i = 0; i < 8; i++)
#pragma unroll
                for (int j = 0; j < 8; j++)
                    acc[i][j] = fmaf(ar[i], br[j], acc[i][j]);
        }
        __syncthreads();
    }

    if (!rope) {
#pragma unroll
        for (int i = 0; i < 8; i++) {
            float* Crow = C + (long long)(m0 + tr + i) * 1024 + n0 + tc;
#pragma unroll
            for (int j = 0; j < 8; j += 4) {
                float4 v = make_float4(acc[i][j], acc[i][j + 1], acc[i][j + 2], acc[i][j + 3]);
                *(float4*)(Crow + j) = v;
            }
        }
    } else {
        // inv[p] = 10000^(-p/32) = 2^(-p * log2(10000)/32)
        float invf[4];
        float bb[8];
#pragma unroll
        for (int jj = 0; jj < 4; jj++) {
            int colg = n0 + tc + jj * 2;
            int p = (colg & 63) >> 1;
            invf[jj] = exp2f(-(float)p * 0.41524101186092029f);
        }
#pragma unroll
        for (int j = 0; j < 8; j++) bb[j] = bias[n0 + tc + j];
#pragma unroll
        for (int i = 0; i < 8; i++) {
            int rowg = m0 + tr + i;
            float pos = (float)(rowg & 1023);
            float* Crow = C + (long long)rowg * 1024 + n0 + tc;
#pragma unroll
            for (int jj = 0; jj < 4; jj++) {
                float sn, cs;
                sincosf(pos * invf[jj], &sn, &cs);
                float v0 = acc[i][2 * jj]     + bb[2 * jj];
                float v1 = acc[i][2 * jj + 1] + bb[2 * jj + 1];
                Crow[2 * jj]     = v0 * cs - v1 * sn;
                Crow[2 * jj + 1] = v1 * cs + v0 * sn;
            }
        }
    }
}

// ---------------------------------------------------------------------------
// Scores + masked softmax for q-row 0. One block per (b,h): grid 64 x 256 thr.
// ---------------------------------------------------------------------------
__global__ __launch_bounds__(256) void scores_kernel(const int* __restrict__ mask,
                                                     const float* __restrict__ q0,
                                                     const float* __restrict__ Kw,
                                                     float* __restrict__ row0)
{
    int b = blockIdx.x >> 4;
    int h = blockIdx.x & 15;
    __shared__ float q[64];
    __shared__ float sc[1024];
    __shared__ float red[8];
    __shared__ float bc;
    int tid = threadIdx.x;
    if (tid < 64) q[tid] = q0[b * 1024 + h * 64 + tid];
    __syncthreads();

    float lmax = -3.4e38f;
#pragma unroll
    for (int it = 0; it < 4; it++) {
        int t = it * 256 + tid;
        const float* kr = Kw + ((long long)(b * 1024 + t)) * 1024 + h * 64;
        float dot = 0.f;
#pragma unroll
        for (int d = 0; d < 64; d += 4) {
            float4 kv = *(const float4*)(kr + d);
            dot = fmaf(q[d], kv.x, dot);
            dot = fmaf(q[d + 1], kv.y, dot);
            dot = fmaf(q[d + 2], kv.z, dot);
            dot = fmaf(q[d + 3], kv.w, dot);
        }
        float s = (mask[b * 1024 + t] == 0) ? -1e9f : dot * 0.125f;
        sc[t] = s;
        lmax = fmaxf(lmax, s);
    }
#pragma unroll
    for (int o = 16; o; o >>= 1) lmax = fmaxf(lmax, __shfl_xor_sync(0xffffffffu, lmax, o));
    if ((tid & 31) == 0) red[tid >> 5] = lmax;
    __syncthreads();
    if (tid == 0) {
        float m = red[0];
        for (int i = 1; i < 8; i++) m = fmaxf(m, red[i]);
        bc = m;
    }
    __syncthreads();
    float gmax = bc;

    float lsum = 0.f;
#pragma unroll
    for (int it = 0; it < 4; it++) {
        int t = it * 256 + tid;
        float e = expf(sc[t] - gmax);
        sc[t] = e;
        lsum += e;
    }
#pragma unroll
    for (int o = 16; o; o >>= 1) lsum += __shfl_xor_sync(0xffffffffu, lsum, o);
    if ((tid & 31) == 0) red[tid >> 5] = lsum;
    __syncthreads();
    if (tid == 0) {
        float s = 0.f;
        for (int i = 0; i < 8; i++) s += red[i];
        bc = 1.f / s;
    }
    __syncthreads();
    float invs = bc;
#pragma unroll
    for (int it = 0; it < 4; it++) {
        int t = it * 256 + tid;
        row0[((long long)(b * 16 + h)) * 1024 + t] = sc[t] * invs;
    }
}

// ---------------------------------------------------------------------------
// Conv1d(16 -> 1024, k=3, pad=1) over row0, + bias + relu.
// grid (4 lchunks, 64 o-groups of 16, 4 b), 256 threads; thread = one l, 16 o.
// ---------------------------------------------------------------------------
#define OPB 16
__global__ __launch_bounds__(256) void conv_kernel(const float* __restrict__ cw,
                                                   const float* __restrict__ cb,
                                                   const float* __restrict__ row0,
                                                   float* __restrict__ out)
{
    int lc = blockIdx.x, og = blockIdx.y, b = blockIdx.z;
    __shared__ float tile[16][264];   // 258 used
    __shared__ float ws[OPB * 48];
    __shared__ float wb[OPB];
    int tid = threadIdx.x;

    for (int idx = tid; idx < OPB * 48; idx += 256) {
        int o = og * OPB + idx / 48;
        ws[idx] = cw[o * 48 + (idx % 48)];
    }
    if (tid < OPB) wb[tid] = cb[og * OPB + tid];
    for (int idx = tid; idx < 16 * 258; idx += 256) {
        int c = idx / 258, x = idx % 258;
        int l = lc * 256 - 1 + x;
        tile[c][x] = (l >= 0 && l < SS) ? row0[((long long)(b * 16 + c)) * SS + l] : 0.f;
    }
    __syncthreads();

    float acc[OPB];
#pragma unroll
    for (int o = 0; o < OPB; o++) acc[o] = wb[o];
#pragma unroll
    for (int c = 0; c < 16; c++) {
        float r0 = tile[c][tid], r1 = tile[c][tid + 1], r2 = tile[c][tid + 2];
#pragma unroll
        for (int o = 0; o < OPB; o++) {
            acc[o] = fmaf(r0, ws[o * 48 + c * 3],     acc[o]);
            acc[o] = fmaf(r1, ws[o * 48 + c * 3 + 1], acc[o]);
            acc[o] = fmaf(r2, ws[o * 48 + c * 3 + 2], acc[o]);
        }
    }
    int l = lc * 256 + tid;
#pragma unroll
    for (int o = 0; o < OPB; o++)
        out[((long long)(b * 1024 + og * OPB + o)) * SS + l] = fmaxf(acc[o], 0.f);
}

// ---------------------------------------------------------------------------
extern "C" void kernel_launch(void* const* d_in, const int* in_sizes, int n_in,
                              void* d_out, int out_size)
{
    const float* X    = (const float*)d_in[0];
    const int*   mask = (const int*)d_in[1];
    const float* W_G  = (const float*)d_in[2];
    const float* b_G  = (const float*)d_in[3];
    const float* Wq   = (const float*)d_in[4];
    const float* bq   = (const float*)d_in[5];
    const float* Wk   = (const float*)d_in[6];
    const float* bk   = (const float*)d_in[7];
    const float* cw   = (const float*)d_in[8];
    const float* cb   = (const float*)d_in[9];
    float* out = (float*)d_out;

    float *pWGK, *pbiask, *pg0, *pq0, *pKw, *prow0;
    cudaGetSymbolAddress((void**)&pWGK,   g_WGK);
    cudaGetSymbolAddress((void**)&pbiask, g_biask);
    cudaGetSymbolAddress((void**)&pg0,    g_g0);
    cudaGetSymbolAddress((void**)&pq0,    g_q0);
    cudaGetSymbolAddress((void**)&pKw,    g_Kw);
    cudaGetSymbolAddress((void**)&prow0,  g_row0);

    // biask = b_G @ Wk + bk
    gemv_kernel<<<dim3(32, 1), 32>>>(b_G, Wk, bk, pbiask, 0LL);
    // g0 = X[:,0,:] @ W_G + b_G ; q0 = g0 @ Wq + bq (rope@0 = identity)
    gemv_kernel<<<dim3(32, 4), 32>>>(X, W_G, b_G, pg0, (long long)SS * DD);
    gemv_kernel<<<dim3(32, 4), 32>>>(pg0, Wq, bq, pq0, 1024LL);
    // WGK = W_G @ Wk
    sgemm128<<<dim3(8, 8), 256>>>(W_G, Wk, nullptr, pWGK, 0);
    // Kw = rope(X @ WGK + biask)
    sgemm128<<<dim3(8, 32), 256>>>(X, pWGK, pbiask, pKw, 1);
    // row0 = softmax(mask(q0 . Kw / 8))
    scores_kernel<<<64, 256>>>(mask, pq0, pKw, prow0);
    // out = relu(conv1d(row0) + cb)
    conv_kernel<<<dim3(4, 64, 4), 256>>>(cw, cb, prow0, out);
}

// round 5
// speedup vs baseline: 1.5365x; 1.5365x over previous
#include <cuda_runtime.h>
#include <cuda_bf16.h>
#include <cstdint>
#include <math.h>

#define BB 4
#define SS 1024
#define DD 1024
#define HH 16
#define DKK 64

// ---------------------------------------------------------------------------
// Portable PTX helpers (sm_80+: mma.sync bf16, ldmatrix, cp.async)
// ---------------------------------------------------------------------------
__device__ __forceinline__ uint32_t smem_u32(const void* p) {
    uint32_t a;
    asm("{ .reg .u64 t; cvta.to.shared.u64 t, %1; cvt.u32.u64 %0, t; }" : "=r"(a) : "l"(p));
    return a;
}
#define CPASYNC16(dst, src) \
    asm volatile("cp.async.cg.shared.global [%0], [%1], 16;" :: "r"(dst), "l"(src) : "memory")
#define CPCOMMIT() asm volatile("cp.async.commit_group;" ::: "memory")
#define CPWAIT1()  asm volatile("cp.async.wait_group 1;" ::: "memory")
#define CPWAIT0()  asm volatile("cp.async.wait_group 0;" ::: "memory")

#define LDSM4(r0, r1, r2, r3, addr) \
    asm volatile("ldmatrix.sync.aligned.m8n8.x4.shared.b16 {%0,%1,%2,%3}, [%4];" \
                 : "=r"(r0), "=r"(r1), "=r"(r2), "=r"(r3) : "r"(addr))

#define MMA16816(c, a, b) \
    asm volatile("mma.sync.aligned.m16n8k16.row.col.f32.bf16.bf16.f32 " \
                 "{%0,%1,%2,%3},{%4,%5,%6,%7},{%8,%9},{%0,%1,%2,%3};" \
                 : "+f"((c)[0]), "+f"((c)[1]), "+f"((c)[2]), "+f"((c)[3]) \
                 : "r"((a)[0]), "r"((a)[1]), "r"((a)[2]), "r"((a)[3]), \
                   "r"((b)[0]), "r"((b)[1]))

// ---------------------------------------------------------------------------
// Scratch (static device globals)
// ---------------------------------------------------------------------------
__device__ __nv_bfloat16 g_Xhi[BB * SS * DD];
__device__ __nv_bfloat16 g_Xlo[BB * SS * DD];
__device__ __nv_bfloat16 g_WGhi[DD * DD];
__device__ __nv_bfloat16 g_WGlo[DD * DD];
__device__ __nv_bfloat16 g_WkThi[DD * DD];
__device__ __nv_bfloat16 g_WkTlo[DD * DD];
__device__ __nv_bfloat16 g_WGKThi[DD * DD];
__device__ __nv_bfloat16 g_WGKTlo[DD * DD];
__device__ float g_Kw[BB * SS * DD];
__device__ float g_biask[DD];
__device__ float g_g0[BB * DD];
__device__ float g_q0[BB * DD];
__device__ float g_row0[BB * HH * SS];

// ---------------------------------------------------------------------------
// fp32 -> bf16 hi/lo split
// ---------------------------------------------------------------------------
__global__ void split_kernel(const float4* __restrict__ in,
                             __nv_bfloat162* __restrict__ hi,
                             __nv_bfloat162* __restrict__ lo, int n4)
{
    int i = blockIdx.x * 256 + threadIdx.x;
    if (i >= n4) return;
    float4 v = in[i];
    __nv_bfloat16 hx = __float2bfloat16(v.x), hy = __float2bfloat16(v.y);
    __nv_bfloat16 hz = __float2bfloat16(v.z), hw = __float2bfloat16(v.w);
    __nv_bfloat162 a, b;
    a.x = hx; a.y = hy; b.x = hz; b.y = hw;
    hi[2 * i] = a; hi[2 * i + 1] = b;
    __nv_bfloat162 c, d;
    c.x = __float2bfloat16(v.x - __bfloat162float(hx));
    c.y = __float2bfloat16(v.y - __bfloat162float(hy));
    d.x = __float2bfloat16(v.z - __bfloat162float(hz));
    d.y = __float2bfloat16(v.w - __bfloat162float(hw));
    lo[2 * i] = c; lo[2 * i + 1] = d;
}

// Transpose + split: out[c][r] = in[r][c], 1024x1024
__global__ void transpose_split_kernel(const float* __restrict__ in,
                                       __nv_bfloat16* __restrict__ thi,
                                       __nv_bfloat16* __restrict__ tlo)
{
    __shared__ float t[32][33];
    int c0 = blockIdx.x * 32, r0 = blockIdx.y * 32;
    int tx = threadIdx.x, ty = threadIdx.y;
#pragma unroll
    for (int k = 0; k < 4; k++)
        t[ty + 8 * k][tx] = in[(size_t)(r0 + ty + 8 * k) * 1024 + c0 + tx];
    __syncthreads();
#pragma unroll
    for (int k = 0; k < 4; k++) {
        float v = t[tx][ty + 8 * k];
        __nv_bfloat16 h = __float2bfloat16(v);
        size_t o = (size_t)(c0 + ty + 8 * k) * 1024 + r0 + tx;
        thi[o] = h;
        tlo[o] = __float2bfloat16(v - __bfloat162float(h));
    }
}

// ---------------------------------------------------------------------------
// Small GEMV
// ---------------------------------------------------------------------------
__global__ void gemv_kernel(const float* __restrict__ x,
                            const float* __restrict__ W,
                            const float* __restrict__ bv,
                            float* __restrict__ out,
                            long long xstride)
{
    int b = blockIdx.y;
    int j = blockIdx.x * 32 + threadIdx.x;
    const float* xr = x + (long long)b * xstride;
    float acc = bv[j];
#pragma unroll 8
    for (int i = 0; i < 1024; i++)
        acc = fmaf(xr[i], W[(long long)i * 1024 + j], acc);
    out[b * 1024 + j] = acc;
}

// ---------------------------------------------------------------------------
// mma.sync bf16 GEMM: C[m,n] = sum_k A[m,k]*B[n,k], 3-term hi/lo split.
// CTA 128x128, 8 warps (2m x 4n), warp tile 64x32. K chunks of 32, 2-stage
// cp.async pipeline. smem row = 128B: [hi k0..31 | lo k0..31], SW128 swizzle.
// mode 0: split-write bf16 Chi/Clo ; mode 1: Cf = rope(v + bias)
// ---------------------------------------------------------------------------
__global__ __launch_bounds__(256) void mmagemm(
    const __nv_bfloat16* __restrict__ Ahi, const __nv_bfloat16* __restrict__ Alo,
    const __nv_bfloat16* __restrict__ Bhi, const __nv_bfloat16* __restrict__ Blo,
    int mode,
    const float* __restrict__ bias, float* __restrict__ Cf,
    __nv_bfloat16* __restrict__ Chi, __nv_bfloat16* __restrict__ Clo)
{
    extern __shared__ char dyn[];
    uint32_t dynb = smem_u32(dyn);
    const uint32_t sbase = (dynb + 1023) & ~1023u;   // 1KB-aligned smem base

    const int tid = threadIdx.x;
    const int wid = tid >> 5, lane = tid & 31;
    const int gid = lane >> 2, tig = lane & 3;
    const int m0 = blockIdx.y * 128, n0 = blockIdx.x * 128;
    const int wm = (wid >> 2) * 64;     // warp m offset (0 / 64)
    const int wn = (wid & 3) * 32;      // warp n offset (0..96)

    // ---- cp.async task precompute: 4 A-tasks + 4 B-tasks per thread -------
    const __nv_bfloat16* aSrc[4];
    const __nv_bfloat16* bSrc[4];
    uint32_t aDst[4], bDst[4];
#pragma unroll
    for (int it = 0; it < 4; it++) {
        int ix = it * 256 + tid;
        int r = ix >> 3, seg = ix & 7;      // r: row 0..127 ; seg: 16B segment
        const __nv_bfloat16* ah = (seg < 4) ? Ahi : Alo;
        const __nv_bfloat16* bh = (seg < 4) ? Bhi : Blo;
        aSrc[it] = ah + (size_t)(m0 + r) * 1024 + (seg & 3) * 8;
        bSrc[it] = bh + (size_t)(n0 + r) * 1024 + (seg & 3) * 8;
        uint32_t off = r * 128 + ((seg * 16) ^ ((r & 7) << 4));
        aDst[it] = sbase + off;
        bDst[it] = sbase + 16384 + off;
    }

    // ---- ldmatrix address precompute ---------------------------------------
    const uint32_t xorv = (lane & 7) << 4;          // swizzle XOR (const/thread)
    const uint32_t ksel = (lane >> 4) * 16;         // k-half selector
    uint32_t aRow[4], bRow[2];
#pragma unroll
    for (int mt = 0; mt < 4; mt++) aRow[mt] = (wm + mt * 16 + (lane & 15)) * 128;
#pragma unroll
    for (int ng = 0; ng < 2; ng++)  bRow[ng] = (wn + ng * 16 + (lane & 15)) * 128;

    float acc[4][4][4];
#pragma unroll
    for (int mt = 0; mt < 4; mt++)
#pragma unroll
        for (int nt = 0; nt < 4; nt++)
#pragma unroll
            for (int i = 0; i < 4; i++) acc[mt][nt][i] = 0.f;

    // ---- prologue: chunk 0 into stage 0 ------------------------------------
#pragma unroll
    for (int it = 0; it < 4; it++) {
        CPASYNC16(aDst[it], aSrc[it]);
        CPASYNC16(bDst[it], bSrc[it]);
    }
    CPCOMMIT();

#pragma unroll 1
    for (int ch = 0; ch < 32; ch++) {
        const int s = ch & 1;
        if (ch < 31) {
            const uint32_t so = (s ^ 1) * 32768;
            const int ko = (ch + 1) * 32;
#pragma unroll
            for (int it = 0; it < 4; it++) {
                CPASYNC16(aDst[it] + so, aSrc[it] + ko);
                CPASYNC16(bDst[it] + so, bSrc[it] + ko);
            }
            CPCOMMIT();
            CPWAIT1();
        } else {
            CPWAIT0();
        }
        __syncthreads();

        const uint32_t As = sbase + s * 32768;
        const uint32_t Bs = As + 16384;
#pragma unroll
        for (int ks = 0; ks < 2; ks++) {
            const uint32_t khi = (ks * 32 + ksel) ^ xorv;
            const uint32_t klo = (64 + ks * 32 + ksel) ^ xorv;
            uint32_t ah[4][4], al[4][4], bh[4][2], bl[4][2];
#pragma unroll
            for (int mt = 0; mt < 4; mt++) {
                LDSM4(ah[mt][0], ah[mt][1], ah[mt][2], ah[mt][3], As + aRow[mt] + khi);
                LDSM4(al[mt][0], al[mt][1], al[mt][2], al[mt][3], As + aRow[mt] + klo);
            }
#pragma unroll
            for (int ng = 0; ng < 2; ng++) {
                uint32_t r0, r1, r2, r3;
                LDSM4(r0, r1, r2, r3, Bs + bRow[ng] + khi);
                bh[2 * ng][0] = r0; bh[2 * ng][1] = r2;
                bh[2 * ng + 1][0] = r1; bh[2 * ng + 1][1] = r3;
                LDSM4(r0, r1, r2, r3, Bs + bRow[ng] + klo);
                bl[2 * ng][0] = r0; bl[2 * ng][1] = r2;
                bl[2 * ng + 1][0] = r1; bl[2 * ng + 1][1] = r3;
            }
#pragma unroll
            for (int mt = 0; mt < 4; mt++)
#pragma unroll
                for (int nt = 0; nt < 4; nt++) {
                    MMA16816(acc[mt][nt], ah[mt], bh[nt]);
                    MMA16816(acc[mt][nt], ah[mt], bl[nt]);
                    MMA16816(acc[mt][nt], al[mt], bh[nt]);
                }
        }
        __syncthreads();
    }

    // ---- epilogue (direct from registers; acc pairs = even/odd col pairs) --
    if (mode == 1) {
#pragma unroll
        for (int mt = 0; mt < 4; mt++) {
#pragma unroll
            for (int half = 0; half < 2; half++) {
                int row = m0 + wm + mt * 16 + gid + half * 8;
                float pos = (float)(row & 1023);
#pragma unroll
                for (int nt = 0; nt < 4; nt++) {
                    int col = n0 + wn + nt * 8 + 2 * tig;
                    int p = (col & 63) >> 1;
                    float inv = exp2f(-(float)p * 0.41524101186092029f);
                    float sn, cs;
                    sincosf(pos * inv, &sn, &cs);
                    float v0 = acc[mt][nt][half * 2]     + __ldg(bias + col);
                    float v1 = acc[mt][nt][half * 2 + 1] + __ldg(bias + col + 1);
                    float2 o;
                    o.x = v0 * cs - v1 * sn;
                    o.y = v1 * cs + v0 * sn;
                    *(float2*)(Cf + (size_t)row * 1024 + col) = o;
                }
            }
        }
    } else {
#pragma unroll
        for (int mt = 0; mt < 4; mt++) {
#pragma unroll
            for (int half = 0; half < 2; half++) {
                int row = m0 + wm + mt * 16 + gid + half * 8;
#pragma unroll
                for (int nt = 0; nt < 4; nt++) {
                    int col = n0 + wn + nt * 8 + 2 * tig;
                    float v0 = acc[mt][nt][half * 2];
                    float v1 = acc[mt][nt][half * 2 + 1];
                    __nv_bfloat16 h0 = __float2bfloat16(v0);
                    __nv_bfloat16 h1 = __float2bfloat16(v1);
                    __nv_bfloat162 hp, lp;
                    hp.x = h0; hp.y = h1;
                    lp.x = __float2bfloat16(v0 - __bfloat162float(h0));
                    lp.y = __float2bfloat16(v1 - __bfloat162float(h1));
                    size_t o = (size_t)row * 1024 + col;
                    *(__nv_bfloat162*)(Chi + o) = hp;
                    *(__nv_bfloat162*)(Clo + o) = lp;
                }
            }
        }
    }
}

// ---------------------------------------------------------------------------
// Scores + masked softmax for q-row 0
// ---------------------------------------------------------------------------
__global__ __launch_bounds__(256) void scores_kernel(const int* __restrict__ mask,
                                                     const float* __restrict__ q0,
                                                     const float* __restrict__ Kw,
                                                     float* __restrict__ row0)
{
    int b = blockIdx.x >> 4;
    int h = blockIdx.x & 15;
    __shared__ float q[64];
    __shared__ float sc[1024];
    __shared__ float red[8];
    __shared__ float bc;
    int tid = threadIdx.x;
    if (tid < 64) q[tid] = q0[b * 1024 + h * 64 + tid];
    __syncthreads();

    float lmax = -3.4e38f;
#pragma unroll
    for (int it = 0; it < 4; it++) {
        int t = it * 256 + tid;
        const float* kr = Kw + ((long long)(b * 1024 + t)) * 1024 + h * 64;
        float dot = 0.f;
#pragma unroll
        for (int d = 0; d < 64; d += 4) {
            float4 kv = *(const float4*)(kr + d);
            dot = fmaf(q[d], kv.x, dot);
            dot = fmaf(q[d + 1], kv.y, dot);
            dot = fmaf(q[d + 2], kv.z, dot);
            dot = fmaf(q[d + 3], kv.w, dot);
        }
        float s = (mask[b * 1024 + t] == 0) ? -1e9f : dot * 0.125f;
        sc[t] = s;
        lmax = fmaxf(lmax, s);
    }
#pragma unroll
    for (int o = 16; o; o >>= 1) lmax = fmaxf(lmax, __shfl_xor_sync(0xffffffffu, lmax, o));
    if ((tid & 31) == 0) red[tid >> 5] = lmax;
    __syncthreads();
    if (tid == 0) {
        float m = red[0];
        for (int i = 1; i < 8; i++) m = fmaxf(m, red[i]);
        bc = m;
    }
    __syncthreads();
    float gmax = bc;

    float lsum = 0.f;
#pragma unroll
    for (int it = 0; it < 4; it++) {
        int t = it * 256 + tid;
        float e = expf(sc[t] - gmax);
        sc[t] = e;
        lsum += e;
    }
#pragma unroll
    for (int o = 16; o; o >>= 1) lsum += __shfl_xor_sync(0xffffffffu, lsum, o);
    if ((tid & 31) == 0) red[tid >> 5] = lsum;
    __syncthreads();
    if (tid == 0) {
        float s = 0.f;
        for (int i = 0; i < 8; i++) s += red[i];
        bc = 1.f / s;
    }
    __syncthreads();
    float invs = bc;
#pragma unroll
    for (int it = 0; it < 4; it++) {
        int t = it * 256 + tid;
        row0[((long long)(b * 16 + h)) * 1024 + t] = sc[t] * invs;
    }
}

// ---------------------------------------------------------------------------
// Conv1d(16 -> 1024, k=3, pad=1) + bias + relu
// ---------------------------------------------------------------------------
#define OPB 16
__global__ __launch_bounds__(256) void conv_kernel(const float* __restrict__ cw,
                                                   const float* __restrict__ cb,
                                                   const float* __restrict__ row0,
                                                   float* __restrict__ out)
{
    int lc = blockIdx.x, og = blockIdx.y, b = blockIdx.z;
    __shared__ float tile[16][264];
    __shared__ float ws[OPB * 48];
    __shared__ float wb[OPB];
    int tid = threadIdx.x;

    for (int idx = tid; idx < OPB * 48; idx += 256) {
        int o = og * OPB + idx / 48;
        ws[idx] = cw[o * 48 + (idx % 48)];
    }
    if (tid < OPB) wb[tid] = cb[og * OPB + tid];
    for (int idx = tid; idx < 16 * 258; idx += 256) {
        int c = idx / 258, x = idx % 258;
        int l = lc * 256 - 1 + x;
        tile[c][x] = (l >= 0 && l < SS) ? row0[((long long)(b * 16 + c)) * SS + l] : 0.f;
    }
    __syncthreads();

    float acc[OPB];
#pragma unroll
    for (int o = 0; o < OPB; o++) acc[o] = wb[o];
#pragma unroll
    for (int c = 0; c < 16; c++) {
        float r0 = tile[c][tid], r1 = tile[c][tid + 1], r2 = tile[c][tid + 2];
#pragma unroll
        for (int o = 0; o < OPB; o++) {
            acc[o] = fmaf(r0, ws[o * 48 + c * 3],     acc[o]);
            acc[o] = fmaf(r1, ws[o * 48 + c * 3 + 1], acc[o]);
            acc[o] = fmaf(r2, ws[o * 48 + c * 3 + 2], acc[o]);
        }
    }
    int l = lc * 256 + tid;
#pragma unroll
    for (int o = 0; o < OPB; o++)
        out[((long long)(b * 1024 + og * OPB + o)) * SS + l] = fmaxf(acc[o], 0.f);
}

// ---------------------------------------------------------------------------
extern "C" void kernel_launch(void* const* d_in, const int* in_sizes, int n_in,
                              void* d_out, int out_size)
{
    const float* X    = (const float*)d_in[0];
    const int*   mask = (const int*)d_in[1];
    const float* W_G  = (const float*)d_in[2];
    const float* b_G  = (const float*)d_in[3];
    const float* Wq   = (const float*)d_in[4];
    const float* bq   = (const float*)d_in[5];
    const float* Wk   = (const float*)d_in[6];
    const float* bk   = (const float*)d_in[7];
    const float* cw   = (const float*)d_in[8];
    const float* cb   = (const float*)d_in[9];
    float* out = (float*)d_out;

    __nv_bfloat16 *pXhi, *pXlo, *pWGhi, *pWGlo, *pWkThi, *pWkTlo, *pCThi, *pCTlo;
    float *pKw, *pbiask, *pg0, *pq0, *prow0;
    cudaGetSymbolAddress((void**)&pXhi,   g_Xhi);
    cudaGetSymbolAddress((void**)&pXlo,   g_Xlo);
    cudaGetSymbolAddress((void**)&pWGhi,  g_WGhi);
    cudaGetSymbolAddress((void**)&pWGlo,  g_WGlo);
    cudaGetSymbolAddress((void**)&pWkThi, g_WkThi);
    cudaGetSymbolAddress((void**)&pWkTlo, g_WkTlo);
    cudaGetSymbolAddress((void**)&pCThi,  g_WGKThi);
    cudaGetSymbolAddress((void**)&pCTlo,  g_WGKTlo);
    cudaGetSymbolAddress((void**)&pKw,    g_Kw);
    cudaGetSymbolAddress((void**)&pbiask, g_biask);
    cudaGetSymbolAddress((void**)&pg0,    g_g0);
    cudaGetSymbolAddress((void**)&pq0,    g_q0);
    cudaGetSymbolAddress((void**)&prow0,  g_row0);

    static int smem_set = 0;
    if (!smem_set) {
        cudaFuncSetAttribute(mmagemm, cudaFuncAttributeMaxDynamicSharedMemorySize, 66560);
        smem_set = 1;
    }

    // Conversions
    split_kernel<<<4096, 256>>>((const float4*)X, (__nv_bfloat162*)pXhi,
                                (__nv_bfloat162*)pXlo, BB * SS * DD / 4);
    split_kernel<<<1024, 256>>>((const float4*)W_G, (__nv_bfloat162*)pWGhi,
                                (__nv_bfloat162*)pWGlo, DD * DD / 4);
    transpose_split_kernel<<<dim3(32, 32), dim3(32, 8)>>>(Wk, pWkThi, pWkTlo);

    // Small GEMVs: biask = b_G@Wk + bk ; q0 = (X0@W_G + b_G)@Wq + bq
    gemv_kernel<<<dim3(32, 1), 32>>>(b_G, Wk, bk, pbiask, 0LL);
    gemv_kernel<<<dim3(32, 4), 32>>>(X, W_G, b_G, pg0, (long long)SS * DD);
    gemv_kernel<<<dim3(32, 4), 32>>>(pg0, Wq, bq, pq0, 1024LL);

    // GEMM1: C[n_out,k] = WGK^T  (A = Wk^T, B = W_G), split-write bf16
    mmagemm<<<dim3(8, 8), 256, 66560>>>(pWkThi, pWkTlo, pWGhi, pWGlo, 0,
                                        nullptr, nullptr, pCThi, pCTlo);
    // GEMM2: Kw = rope(X @ WGK + biask)
    mmagemm<<<dim3(8, 32), 256, 66560>>>(pXhi, pXlo, pCThi, pCTlo, 1,
                                         pbiask, pKw, nullptr, nullptr);

    scores_kernel<<<64, 256>>>(mask, pq0, pKw, prow0);
    conv_kernel<<<dim3(4, 64, 4), 256>>>(cw, cb, prow0, out);
}